// round 12
// baseline (speedup 1.0000x reference)
#include <cuda_runtime.h>
#include <cstdint>

#define RMAX 32
#define SMAX 2
#define CZ    128              // channels
#define NPOS  66               // 2*(RMAX+1)
#define NN    1024             // fast-path N
#define UCOLS 128              // columns per CTA work unit (2 TMA tiles)
#define TCOLS 64               // columns per TMA tile
#define TILE_BYTES (TCOLS * CZ * 4)   // 32 KB
#define NBUF  2

// Identity (NPOS==66 makes combined-table rows coincide with W rows):
//   u < 66   : p-vec = W[u] + W[131]   (W_tok[65])
//   66<=u<132: p-vec = W[u] + W[32]    (W_pos[32])
//   chain    : + W[133 + cRel] + (cRel<5 ? W[132] : 0)
// All addends loaded on demand (L1-hot); no long-lived fold registers
// (R10 proved resident fold registers trigger a 40us spill pathology).

__device__ __forceinline__ int pack_idx(int ai, int ri, int ei, int si, int ti,
                                        int aj, int rj, int ej, int sj, int tj)
{
    bool sc = (ai == aj);
    bool sr = (ri == rj);
    bool se = (ei == ej);
    int u;
    if (sc && sr)  u = NPOS + min(max(ti - tj + RMAX, 0), 2 * RMAX);
    else if (sc)   u = min(max(ri - rj + RMAX, 0), 2 * RMAX);
    else           u = 2 * RMAX + 1;
    int cRel = se ? min(max(si - sj + SMAX, 0), 2 * SMAX) : (2 * SMAX + 1);
    return u | (cRel << 8);
}

__global__ __launch_bounds__(1024, 2)
void relpos_tma(const int* __restrict__ asym,
                const int* __restrict__ resi,
                const int* __restrict__ ent,
                const int* __restrict__ sym,
                const int* __restrict__ tok,
                const float* __restrict__ W,
                float* __restrict__ out)
{
    extern __shared__ char smem[];
    float* tiles = (float*)smem;                        // [NBUF][TILE_BYTES/4]
    int*   sI    = (int*)(smem + NBUF * TILE_BYTES);    // [UCOLS]

    uint32_t sbase;
    asm("{ .reg .u64 t; cvta.to.shared.u64 t, %1; cvt.u32.u64 %0, t; }"
        : "=r"(sbase) : "l"(smem));

    const int tid  = threadIdx.x;
    const int lane = tid & 31;

    const float4* W4 = (const float4*)W;

    // Thread tid permanently owns global column j = tid (NN == blockDim).
    const int aj = asym[tid], rj = resi[tid], ej = ent[tid];
    const int sj = sym[tid],  tj = tok[tid];

    // Cross-unit memoization: p is the complete lookup state.
    int pprev = -1;
    float4 s = make_float4(0.f, 0.f, 0.f, 0.f);

    const int upr    = NN / UCOLS;      // 8 units per row
    const int nUnits = NN * upr;        // 8192  (8192/304 = 26.95 -> 0.2% tail)

    for (int v = blockIdx.x; v < nUnits; v += gridDim.x) {
        const int i  = v >> 3;          // row        (upr == 8)
        const int cb = v & (upr - 1);   // column block

        // Owning threads (those whose column lies in this unit) pack indices.
        if ((tid >> 7) == cb) {
            const int ai = __ldg(&asym[i]), ri = __ldg(&resi[i]);
            const int ei = __ldg(&ent[i]),  si = __ldg(&sym[i]);
            const int ti = __ldg(&tok[i]);
            sI[tid & (UCOLS - 1)] = pack_idx(ai, ri, ei, si, ti, aj, rj, ej, sj, tj);
        }

        const size_t unit_base = ((size_t)i * NN + (size_t)cb * UCOLS) * CZ; // floats

        #pragma unroll 1
        for (int t = 0; t < UCOLS / TCOLS; ++t) {       // 2 tiles
            const int      b       = t & 1;
            float*         buf     = tiles + b * (TILE_BYTES / 4);
            const uint32_t bufaddr = sbase + b * TILE_BYTES;

            // Buffer b free once the bulk group that last read it completed.
            if (tid == 0)
                asm volatile("cp.async.bulk.wait_group.read 1;" ::: "memory");
            __syncthreads();   // buffer free for all; sI visible (t==0)

            // Fill the 64-col tile: 2048 float4s, 2 per thread.
            #pragma unroll
            for (int k = 0; k < 2; ++k) {
                const int col = (tid + k * 1024) >> 5;      // 0..63
                const int p   = sI[t * TCOLS + col];        // warp-uniform broadcast
                if (p != pprev) {                           // warp-uniform branch
                    pprev = p;
                    const int rU   = p & 0xFF;
                    const int cRel = p >> 8;
                    const int rX   = (rU < NPOS) ? (NPOS + 65) : 32;
                    float4 a  = __ldg(&W4[rU * 32 + lane]);
                    float4 x1 = __ldg(&W4[rX * 32 + lane]);
                    float4 ch = __ldg(&W4[(2 * NPOS + 1 + cRel) * 32 + lane]);
                    s.x = a.x + x1.x + ch.x;
                    s.y = a.y + x1.y + ch.y;
                    s.z = a.z + x1.z + ch.z;
                    s.w = a.w + x1.w + ch.w;
                    if (cRel < 5) {
                        float4 e = __ldg(&W4[(2 * NPOS) * 32 + lane]);
                        s.x += e.x; s.y += e.y; s.z += e.z; s.w += e.w;
                    }
                }
                ((float4*)buf)[col * 32 + lane] = s;        // STS.128, conflict-free
            }
            __syncthreads();   // tile complete

            if (tid == 0) {
                asm volatile("fence.proxy.async.shared::cta;" ::: "memory");
                const float* dst = out + unit_base + (size_t)t * TCOLS * CZ;
                uint64_t gdst;
                asm("cvta.to.global.u64 %0, %1;" : "=l"(gdst) : "l"(dst));
                asm volatile(
                    "cp.async.bulk.global.shared::cta.bulk_group [%0], [%1], %2;"
                    :: "l"(gdst), "r"(bufaddr), "r"((uint32_t)TILE_BYTES)
                    : "memory");
                asm volatile("cp.async.bulk.commit_group;" ::: "memory");
            }
        }
    }
    // Outstanding bulk stores complete before kernel completion is visible.
}

// Generic fallback (any N): one thread per output float4, direct gathers.
__global__ void relpos_simple(const int* __restrict__ asym,
                              const int* __restrict__ resi,
                              const int* __restrict__ ent,
                              const int* __restrict__ sym,
                              const int* __restrict__ tok,
                              const float* __restrict__ W,
                              float* __restrict__ out,
                              int N)
{
    long long idx = (long long)blockIdx.x * blockDim.x + threadIdx.x;
    long long tot = (long long)N * N * (CZ / 4);
    if (idx >= tot) return;
    int f4 = (int)(idx & (CZ / 4 - 1));
    long long ij = idx >> 5;
    int j = (int)(ij % N);
    int i = (int)(ij / N);

    int p = pack_idx(asym[i], resi[i], ent[i], sym[i], tok[i],
                     asym[j], resi[j], ent[j], sym[j], tok[j]);
    int rU   = p & 0xFF;
    int cRel = p >> 8;
    const float4* W4 = (const float4*)W;
    float4 a  = W4[rU * 32 + f4];
    float4 x1 = (rU < NPOS) ? W4[(NPOS + 65) * 32 + f4] : W4[32 * 32 + f4];
    float4 ch = W4[(2 * NPOS + 1 + cRel) * 32 + f4];
    float4 s;
    s.x = a.x + x1.x + ch.x;
    s.y = a.y + x1.y + ch.y;
    s.z = a.z + x1.z + ch.z;
    s.w = a.w + x1.w + ch.w;
    if (cRel < 5) {
        float4 e = W4[(2 * NPOS) * 32 + f4];
        s.x += e.x; s.y += e.y; s.z += e.z; s.w += e.w;
    }
    ((float4*)out)[idx] = s;
}

extern "C" void kernel_launch(void* const* d_in, const int* in_sizes, int n_in,
                              void* d_out, int out_size)
{
    const int*   asym = (const int*)d_in[0];
    const int*   resi = (const int*)d_in[1];
    const int*   ent  = (const int*)d_in[2];
    const int*   sym  = (const int*)d_in[3];
    const int*   tok  = (const int*)d_in[4];
    const float* W    = (const float*)d_in[5];
    float*       out  = (float*)d_out;

    const int N = in_sizes[0];                  // B*N with B==1 -> 1024

    if (N == NN) {
        int nsm = 148;
        cudaDeviceGetAttribute(&nsm, cudaDevAttrMultiProcessorCount, 0);
        const int nUnits = (NN / UCOLS) * NN;
        int grid = 2 * nsm;
        if (grid > nUnits) grid = nUnits;

        const int smem_bytes = NBUF * TILE_BYTES + UCOLS * (int)sizeof(int);
        cudaFuncSetAttribute(relpos_tma,
                             cudaFuncAttributeMaxDynamicSharedMemorySize, smem_bytes);
        relpos_tma<<<grid, 1024, smem_bytes>>>(asym, resi, ent, sym, tok, W, out);
    } else {
        long long tot = (long long)N * N * (CZ / 4);
        int grid = (int)((tot + 255) / 256);
        relpos_simple<<<grid, 256>>>(asym, resi, ent, sym, tok, W, out, N);
    }
}

// round 13
// speedup vs baseline: 1.0035x; 1.0035x over previous
#include <cuda_runtime.h>
#include <cstdint>

#define RMAX 32
#define SMAX 2
#define CZ    128              // channels
#define NPOS  66               // 2*(RMAX+1)
#define NN    1024             // fast-path N
#define HALF  512              // columns per CTA work unit (memo-critical: keep large)
#define TCOLS 64               // columns per TMA tile
#define TILE_BYTES (TCOLS * CZ * 4)   // 32 KB
#define NBUF  2

// Identity (NPOS==66 makes combined-table rows coincide with W rows):
//   u < 66   : p-vec = W[u] + W[131]   (W_tok[65])
//   66<=u<132: p-vec = W[u] + W[32]    (W_pos[32])
//   chain    : + W[133 + cRel] + (cRel<5 ? W[132] : 0)
// Addends loaded on demand (L1-hot); no long-lived fold registers (R10 pathology).

__device__ __forceinline__ int pack_idx(int ai, int ri, int ei, int si, int ti,
                                        int aj, int rj, int ej, int sj, int tj)
{
    bool sc = (ai == aj);
    bool sr = (ri == rj);
    bool se = (ei == ej);
    int u;
    if (sc && sr)  u = NPOS + min(max(ti - tj + RMAX, 0), 2 * RMAX);
    else if (sc)   u = min(max(ri - rj + RMAX, 0), 2 * RMAX);
    else           u = 2 * RMAX + 1;
    int cRel = se ? min(max(si - sj + SMAX, 0), 2 * SMAX) : (2 * SMAX + 1);
    return u | (cRel << 8);
}

__global__ __launch_bounds__(1024, 2)
void relpos_tma(const int* __restrict__ asym,
                const int* __restrict__ resi,
                const int* __restrict__ ent,
                const int* __restrict__ sym,
                const int* __restrict__ tok,
                const float* __restrict__ W,
                float* __restrict__ out)
{
    extern __shared__ char smem[];
    float* tiles = (float*)smem;                        // [NBUF][TILE_BYTES/4]
    int*   sI    = (int*)(smem + NBUF * TILE_BYTES);    // [HALF]

    uint32_t sbase;
    asm("{ .reg .u64 t; cvta.to.shared.u64 t, %1; cvt.u32.u64 %0, t; }"
        : "=r"(sbase) : "l"(smem));

    const int tid  = threadIdx.x;
    const int lane = tid & 31;

    const float4* W4 = (const float4*)W;

    // Thread tid permanently owns global column j = tid (NN == blockDim).
    const int aj = asym[tid], rj = resi[tid], ej = ent[tid];
    const int sj = sym[tid],  tj = tok[tid];

    // Cross-unit memoization: p is the complete lookup state.
    int pprev = -1;
    float4 s = make_float4(0.f, 0.f, 0.f, 0.f);

    const int nUnits = NN * (NN / HALF);    // 2048

    // Contiguous, balanced unit range for this CTA:
    //  - ranges differ by <=1 unit (no 7-vs-6.74 tail idle)
    //  - consecutive units are adjacent halves/rows -> memo stays warm
    const int vlo = (int)((long long)blockIdx.x * nUnits / gridDim.x);
    const int vhi = (int)((long long)(blockIdx.x + 1) * nUnits / gridDim.x);

    for (int v = vlo; v < vhi; ++v) {
        const int i = v >> 1;           // row
        const int h = v & 1;            // half

        // Only owning threads need row scalars (keep live set small).
        if ((tid >> 9) == h) {
            const int ai = __ldg(&asym[i]), ri = __ldg(&resi[i]);
            const int ei = __ldg(&ent[i]),  si = __ldg(&sym[i]);
            const int ti = __ldg(&tok[i]);
            sI[tid & (HALF - 1)] = pack_idx(ai, ri, ei, si, ti, aj, rj, ej, sj, tj);
        }

        const size_t unit_base = ((size_t)i * NN + (size_t)h * HALF) * CZ; // floats

        #pragma unroll 1
        for (int t = 0; t < HALF / TCOLS; ++t) {        // 8 tiles
            const int      b       = t & 1;
            float*         buf     = tiles + b * (TILE_BYTES / 4);
            const uint32_t bufaddr = sbase + b * TILE_BYTES;

            // Buffer b free once the bulk group that last read it completed.
            if (tid == 0)
                asm volatile("cp.async.bulk.wait_group.read 1;" ::: "memory");
            __syncthreads();   // buffer free for all; sI visible (t==0)

            // Fill the 64-col tile: 2048 float4s, 2 per thread.
            #pragma unroll
            for (int k = 0; k < 2; ++k) {
                const int col = (tid + k * 1024) >> 5;      // 0..63
                const int p   = sI[t * TCOLS + col];        // warp-uniform broadcast
                if (p != pprev) {                           // warp-uniform branch
                    pprev = p;
                    const int rU   = p & 0xFF;
                    const int cRel = p >> 8;
                    const int rX   = (rU < NPOS) ? (NPOS + 65) : 32;
                    float4 a  = __ldg(&W4[rU * 32 + lane]);
                    float4 x1 = __ldg(&W4[rX * 32 + lane]);
                    float4 ch = __ldg(&W4[(2 * NPOS + 1 + cRel) * 32 + lane]);
                    s.x = a.x + x1.x + ch.x;
                    s.y = a.y + x1.y + ch.y;
                    s.z = a.z + x1.z + ch.z;
                    s.w = a.w + x1.w + ch.w;
                    if (cRel < 5) {
                        float4 e = __ldg(&W4[(2 * NPOS) * 32 + lane]);
                        s.x += e.x; s.y += e.y; s.z += e.z; s.w += e.w;
                    }
                }
                ((float4*)buf)[col * 32 + lane] = s;        // STS.128, conflict-free
            }
            __syncthreads();   // tile complete

            if (tid == 0) {
                asm volatile("fence.proxy.async.shared::cta;" ::: "memory");
                const float* dst = out + unit_base + (size_t)t * TCOLS * CZ;
                uint64_t gdst;
                asm("cvta.to.global.u64 %0, %1;" : "=l"(gdst) : "l"(dst));
                asm volatile(
                    "cp.async.bulk.global.shared::cta.bulk_group [%0], [%1], %2;"
                    :: "l"(gdst), "r"(bufaddr), "r"((uint32_t)TILE_BYTES)
                    : "memory");
                asm volatile("cp.async.bulk.commit_group;" ::: "memory");
            }
        }
    }
    // Outstanding bulk stores complete before kernel completion is visible.
}

// Generic fallback (any N): one thread per output float4, direct gathers.
__global__ void relpos_simple(const int* __restrict__ asym,
                              const int* __restrict__ resi,
                              const int* __restrict__ ent,
                              const int* __restrict__ sym,
                              const int* __restrict__ tok,
                              const float* __restrict__ W,
                              float* __restrict__ out,
                              int N)
{
    long long idx = (long long)blockIdx.x * blockDim.x + threadIdx.x;
    long long tot = (long long)N * N * (CZ / 4);
    if (idx >= tot) return;
    int f4 = (int)(idx & (CZ / 4 - 1));
    long long ij = idx >> 5;
    int j = (int)(ij % N);
    int i = (int)(ij / N);

    int p = pack_idx(asym[i], resi[i], ent[i], sym[i], tok[i],
                     asym[j], resi[j], ent[j], sym[j], tok[j]);
    int rU   = p & 0xFF;
    int cRel = p >> 8;
    const float4* W4 = (const float4*)W;
    float4 a  = W4[rU * 32 + f4];
    float4 x1 = (rU < NPOS) ? W4[(NPOS + 65) * 32 + f4] : W4[32 * 32 + f4];
    float4 ch = W4[(2 * NPOS + 1 + cRel) * 32 + f4];
    float4 s;
    s.x = a.x + x1.x + ch.x;
    s.y = a.y + x1.y + ch.y;
    s.z = a.z + x1.z + ch.z;
    s.w = a.w + x1.w + ch.w;
    if (cRel < 5) {
        float4 e = W4[(2 * NPOS) * 32 + f4];
        s.x += e.x; s.y += e.y; s.z += e.z; s.w += e.w;
    }
    ((float4*)out)[idx] = s;
}

extern "C" void kernel_launch(void* const* d_in, const int* in_sizes, int n_in,
                              void* d_out, int out_size)
{
    const int*   asym = (const int*)d_in[0];
    const int*   resi = (const int*)d_in[1];
    const int*   ent  = (const int*)d_in[2];
    const int*   sym  = (const int*)d_in[3];
    const int*   tok  = (const int*)d_in[4];
    const float* W    = (const float*)d_in[5];
    float*       out  = (float*)d_out;

    const int N = in_sizes[0];                  // B*N with B==1 -> 1024

    if (N == NN) {
        int nsm = 148;
        cudaDeviceGetAttribute(&nsm, cudaDevAttrMultiProcessorCount, 0);
        const int nUnits = (NN / HALF) * NN;
        int grid = 2 * nsm;
        if (grid > nUnits) grid = nUnits;

        const int smem_bytes = NBUF * TILE_BYTES + HALF * (int)sizeof(int);
        cudaFuncSetAttribute(relpos_tma,
                             cudaFuncAttributeMaxDynamicSharedMemorySize, smem_bytes);
        relpos_tma<<<grid, 1024, smem_bytes>>>(asym, resi, ent, sym, tok, W, out);
    } else {
        long long tot = (long long)N * N * (CZ / 4);
        int grid = (int)((tot + 255) / 256);
        relpos_simple<<<grid, 256>>>(asym, resi, ent, sym, tok, W, out, N);
    }
}

// round 14
// speedup vs baseline: 1.3533x; 1.3486x over previous
#include <cuda_runtime.h>
#include <cstdint>

#define RMAX 32
#define SMAX 2
#define CZ    128              // channels
#define NPOS  66               // 2*(RMAX+1)
#define NN    1024             // fast-path N
#define HALF  512              // columns per CTA work unit (memo-critical: keep large)
#define TCOLS 64               // columns per TMA tile
#define TILE_BYTES (TCOLS * CZ * 4)   // 32 KB
#define NBUF  3                // deeper TMA ring (clean test: no register fold)

// Identity (NPOS==66 makes combined-table rows coincide with W rows):
//   u < 66   : p-vec = W[u] + W[131]   (W_tok[65])
//   66<=u<132: p-vec = W[u] + W[32]    (W_pos[32])
//   chain    : + W[133 + cRel] + (cRel<5 ? W[132] : 0)
// Addends loaded on demand; no long-lived fold registers (R10 spill pathology).
// Schedule MUST stride by gridDim (R13: contiguous ranges scatter the chip's
// in-flight write set and drop DRAM to 50%).

__device__ __forceinline__ int pack_idx(int ai, int ri, int ei, int si, int ti,
                                        int aj, int rj, int ej, int sj, int tj)
{
    bool sc = (ai == aj);
    bool sr = (ri == rj);
    bool se = (ei == ej);
    int u;
    if (sc && sr)  u = NPOS + min(max(ti - tj + RMAX, 0), 2 * RMAX);
    else if (sc)   u = min(max(ri - rj + RMAX, 0), 2 * RMAX);
    else           u = 2 * RMAX + 1;
    int cRel = se ? min(max(si - sj + SMAX, 0), 2 * SMAX) : (2 * SMAX + 1);
    return u | (cRel << 8);
}

__global__ __launch_bounds__(1024, 2)
void relpos_tma(const int* __restrict__ asym,
                const int* __restrict__ resi,
                const int* __restrict__ ent,
                const int* __restrict__ sym,
                const int* __restrict__ tok,
                const float* __restrict__ W,
                float* __restrict__ out)
{
    extern __shared__ char smem[];
    float* tiles = (float*)smem;                        // [NBUF][TILE_BYTES/4]
    int*   sI    = (int*)(smem + NBUF * TILE_BYTES);    // [HALF]

    uint32_t sbase;
    asm("{ .reg .u64 t; cvta.to.shared.u64 t, %1; cvt.u32.u64 %0, t; }"
        : "=r"(sbase) : "l"(smem));

    const int tid  = threadIdx.x;
    const int lane = tid & 31;

    const float4* W4 = (const float4*)W;

    // Thread tid permanently owns global column j = tid (NN == blockDim).
    const int aj = asym[tid], rj = resi[tid], ej = ent[tid];
    const int sj = sym[tid],  tj = tok[tid];

    // Cross-unit memoization: p is the complete lookup state.
    int pprev = -1;
    float4 s = make_float4(0.f, 0.f, 0.f, 0.f);

    const int nUnits = NN * (NN / HALF);    // 2048

    int b = 0;   // TMA buffer ring index, persists across units
    for (int v = blockIdx.x; v < nUnits; v += gridDim.x) {
        const int i = v >> 1;           // row
        const int h = v & 1;            // half

        // Only owning threads need row scalars (keep live set small).
        if ((tid >> 9) == h) {
            const int ai = __ldg(&asym[i]), ri = __ldg(&resi[i]);
            const int ei = __ldg(&ent[i]),  si = __ldg(&sym[i]);
            const int ti = __ldg(&tok[i]);
            sI[tid & (HALF - 1)] = pack_idx(ai, ri, ei, si, ti, aj, rj, ej, sj, tj);
        }

        const size_t unit_base = ((size_t)i * NN + (size_t)h * HALF) * CZ; // floats

        #pragma unroll 1
        for (int t = 0; t < HALF / TCOLS; ++t) {        // 8 tiles
            float*         buf     = tiles + b * (TILE_BYTES / 4);
            const uint32_t bufaddr = sbase + b * TILE_BYTES;

            // Buffer b is free once at most NBUF-1 newer groups are outstanding.
            if (tid == 0)
                asm volatile("cp.async.bulk.wait_group.read %0;" :: "n"(NBUF - 1) : "memory");
            __syncthreads();   // buffer free for all; sI visible (t==0)

            // Fill the 64-col tile: 2048 float4s, 2 per thread.
            #pragma unroll
            for (int k = 0; k < 2; ++k) {
                const int col = (tid + k * 1024) >> 5;      // 0..63
                const int p   = sI[t * TCOLS + col];        // warp-uniform broadcast
                if (p != pprev) {                           // warp-uniform branch
                    pprev = p;
                    const int rU   = p & 0xFF;
                    const int cRel = p >> 8;
                    const int rX   = (rU < NPOS) ? (NPOS + 65) : 32;
                    float4 a  = __ldg(&W4[rU * 32 + lane]);
                    float4 x1 = __ldg(&W4[rX * 32 + lane]);
                    float4 ch = __ldg(&W4[(2 * NPOS + 1 + cRel) * 32 + lane]);
                    s.x = a.x + x1.x + ch.x;
                    s.y = a.y + x1.y + ch.y;
                    s.z = a.z + x1.z + ch.z;
                    s.w = a.w + x1.w + ch.w;
                    if (cRel < 5) {
                        float4 e = __ldg(&W4[(2 * NPOS) * 32 + lane]);
                        s.x += e.x; s.y += e.y; s.z += e.z; s.w += e.w;
                    }
                }
                ((float4*)buf)[col * 32 + lane] = s;        // STS.128, conflict-free
            }
            __syncthreads();   // tile complete

            if (tid == 0) {
                asm volatile("fence.proxy.async.shared::cta;" ::: "memory");
                const float* dst = out + unit_base + (size_t)t * TCOLS * CZ;
                uint64_t gdst;
                asm("cvta.to.global.u64 %0, %1;" : "=l"(gdst) : "l"(dst));
                asm volatile(
                    "cp.async.bulk.global.shared::cta.bulk_group [%0], [%1], %2;"
                    :: "l"(gdst), "r"(bufaddr), "r"((uint32_t)TILE_BYTES)
                    : "memory");
                asm volatile("cp.async.bulk.commit_group;" ::: "memory");
            }
            if (++b == NBUF) b = 0;
        }
    }
    // Outstanding bulk stores complete before kernel completion is visible.
}

// Generic fallback (any N): one thread per output float4, direct gathers.
__global__ void relpos_simple(const int* __restrict__ asym,
                              const int* __restrict__ resi,
                              const int* __restrict__ ent,
                              const int* __restrict__ sym,
                              const int* __restrict__ tok,
                              const float* __restrict__ W,
                              float* __restrict__ out,
                              int N)
{
    long long idx = (long long)blockIdx.x * blockDim.x + threadIdx.x;
    long long tot = (long long)N * N * (CZ / 4);
    if (idx >= tot) return;
    int f4 = (int)(idx & (CZ / 4 - 1));
    long long ij = idx >> 5;
    int j = (int)(ij % N);
    int i = (int)(ij / N);

    int p = pack_idx(asym[i], resi[i], ent[i], sym[i], tok[i],
                     asym[j], resi[j], ent[j], sym[j], tok[j]);
    int rU   = p & 0xFF;
    int cRel = p >> 8;
    const float4* W4 = (const float4*)W;
    float4 a  = W4[rU * 32 + f4];
    float4 x1 = (rU < NPOS) ? W4[(NPOS + 65) * 32 + f4] : W4[32 * 32 + f4];
    float4 ch = W4[(2 * NPOS + 1 + cRel) * 32 + f4];
    float4 s;
    s.x = a.x + x1.x + ch.x;
    s.y = a.y + x1.y + ch.y;
    s.z = a.z + x1.z + ch.z;
    s.w = a.w + x1.w + ch.w;
    if (cRel < 5) {
        float4 e = W4[(2 * NPOS) * 32 + f4];
        s.x += e.x; s.y += e.y; s.z += e.z; s.w += e.w;
    }
    ((float4*)out)[idx] = s;
}

extern "C" void kernel_launch(void* const* d_in, const int* in_sizes, int n_in,
                              void* d_out, int out_size)
{
    const int*   asym = (const int*)d_in[0];
    const int*   resi = (const int*)d_in[1];
    const int*   ent  = (const int*)d_in[2];
    const int*   sym  = (const int*)d_in[3];
    const int*   tok  = (const int*)d_in[4];
    const float* W    = (const float*)d_in[5];
    float*       out  = (float*)d_out;

    const int N = in_sizes[0];                  // B*N with B==1 -> 1024

    if (N == NN) {
        int nsm = 148;
        cudaDeviceGetAttribute(&nsm, cudaDevAttrMultiProcessorCount, 0);
        const int nUnits = (NN / HALF) * NN;
        int grid = 2 * nsm;
        if (grid > nUnits) grid = nUnits;

        const int smem_bytes = NBUF * TILE_BYTES + HALF * (int)sizeof(int);
        cudaFuncSetAttribute(relpos_tma,
                             cudaFuncAttributeMaxDynamicSharedMemorySize, smem_bytes);
        relpos_tma<<<grid, 1024, smem_bytes>>>(asym, resi, ent, sym, tok, W, out);
    } else {
        long long tot = (long long)N * N * (CZ / 4);
        int grid = (int)((tot + 255) / 256);
        relpos_simple<<<grid, 256>>>(asym, resi, ent, sym, tok, W, out, N);
    }
}

// round 15
// speedup vs baseline: 1.3788x; 1.0189x over previous
#include <cuda_runtime.h>
#include <cstdint>

#define RMAX 32
#define SMAX 2
#define CZ    128              // channels
#define NPOS  66               // 2*(RMAX+1)
#define NN    1024             // fast-path N
#define HALF  512              // columns per CTA work unit (memo-critical)
#define TCOLS 64               // columns per TMA tile
#define NTILE (HALF / TCOLS)   // 8 tiles per unit
#define TILE_BYTES (TCOLS * CZ * 4)   // 32 KB
#define NBUF  3

// Identity (NPOS==66 makes combined-table rows coincide with W rows):
//   u < 66   : p-vec = W[u] + W[131]   (W_tok[65])
//   66<=u<132: p-vec = W[u] + W[32]    (W_pos[32])
//   chain    : + W[133 + cRel] + (cRel<5 ? W[132] : 0)
// Addends on demand (no resident fold regs: R10 spill pathology).
// Schedule strides by gridDim (R13: contiguous ranges kill DRAM locality).
// NEW: uniform-tile runs -> fill smem once, TMA-replay to r destinations.

__device__ __forceinline__ int pack_idx(int ai, int ri, int ei, int si, int ti,
                                        int aj, int rj, int ej, int sj, int tj)
{
    bool sc = (ai == aj);
    bool sr = (ri == rj);
    bool se = (ei == ej);
    int u;
    if (sc && sr)  u = NPOS + min(max(ti - tj + RMAX, 0), 2 * RMAX);
    else if (sc)   u = min(max(ri - rj + RMAX, 0), 2 * RMAX);
    else           u = 2 * RMAX + 1;
    int cRel = se ? min(max(si - sj + SMAX, 0), 2 * SMAX) : (2 * SMAX + 1);
    return u | (cRel << 8);
}

__global__ __launch_bounds__(1024, 2)
void relpos_tma(const int* __restrict__ asym,
                const int* __restrict__ resi,
                const int* __restrict__ ent,
                const int* __restrict__ sym,
                const int* __restrict__ tok,
                const float* __restrict__ W,
                float* __restrict__ out)
{
    extern __shared__ char smem[];
    float* tiles = (float*)smem;                                  // [NBUF][TILE_BYTES/4]
    int*   sI    = (int*)(smem + NBUF * TILE_BYTES);              // [HALF]
    int*   sFlag = (int*)(smem + NBUF * TILE_BYTES + HALF * 4);   // [NTILE]

    uint32_t sbase;
    asm("{ .reg .u64 t; cvta.to.shared.u64 t, %1; cvt.u32.u64 %0, t; }"
        : "=r"(sbase) : "l"(smem));

    const int tid  = threadIdx.x;
    const int lane = tid & 31;

    const float4* W4 = (const float4*)W;

    // Thread tid permanently owns global column j = tid (NN == blockDim).
    const int aj = asym[tid], rj = resi[tid], ej = ent[tid];
    const int sj = sym[tid],  tj = tok[tid];

    // Cross-unit memoization: p is the complete lookup state.
    int pprev = -1;
    float4 s = make_float4(0.f, 0.f, 0.f, 0.f);

    const int nUnits = NN * (NN / HALF);    // 2048

    int b = 0;   // TMA buffer ring index, persists across units
    for (int v = blockIdx.x; v < nUnits; v += gridDim.x) {
        const int i = v >> 1;           // row
        const int h = v & 1;            // half

        // Owning threads pack indices for this half-row.
        if ((tid >> 9) == h) {
            const int ai = __ldg(&asym[i]), ri = __ldg(&resi[i]);
            const int ei = __ldg(&ent[i]),  si = __ldg(&sym[i]);
            const int ti = __ldg(&tok[i]);
            sI[tid & (HALF - 1)] = pack_idx(ai, ri, ei, si, ti, aj, rj, ej, sj, tj);
        }
        __syncthreads();   // sI complete

        // 8 threads compute per-tile uniformity flags: p if uniform, else -1.
        if (tid < NTILE) {
            const int base = tid * TCOLS;
            const int p0 = sI[base];
            bool uni = true;
            #pragma unroll 8
            for (int q = 1; q < TCOLS; ++q)
                uni &= (sI[base + q] == p0);
            sFlag[tid] = uni ? p0 : -1;
        }
        __syncthreads();   // sFlag visible

        const size_t unit_base = ((size_t)i * NN + (size_t)h * HALF) * CZ; // floats

        int t = 0;
        while (t < NTILE) {
            // Run of identical uniform tiles starting at t (block-uniform calc).
            const int pt = sFlag[t];
            int r = 1;
            if (pt >= 0)
                while (t + r < NTILE && sFlag[t + r] == pt) ++r;

            float*         buf     = tiles + b * (TILE_BYTES / 4);
            const uint32_t bufaddr = sbase + b * TILE_BYTES;

            // Buffer b free once at most NBUF-1 newer groups are outstanding.
            if (tid == 0)
                asm volatile("cp.async.bulk.wait_group.read %0;" :: "n"(NBUF - 1) : "memory");
            __syncthreads();

            // Fill the tile once (covers all r destinations of the run).
            #pragma unroll
            for (int k = 0; k < 2; ++k) {
                const int col = (tid + k * 1024) >> 5;      // 0..63
                const int p   = sI[t * TCOLS + col];        // warp-uniform broadcast
                if (p != pprev) {                           // warp-uniform branch
                    pprev = p;
                    const int rU   = p & 0xFF;
                    const int cRel = p >> 8;
                    const int rX   = (rU < NPOS) ? (NPOS + 65) : 32;
                    float4 a  = __ldg(&W4[rU * 32 + lane]);
                    float4 x1 = __ldg(&W4[rX * 32 + lane]);
                    float4 ch = __ldg(&W4[(2 * NPOS + 1 + cRel) * 32 + lane]);
                    s.x = a.x + x1.x + ch.x;
                    s.y = a.y + x1.y + ch.y;
                    s.z = a.z + x1.z + ch.z;
                    s.w = a.w + x1.w + ch.w;
                    if (cRel < 5) {
                        float4 e = __ldg(&W4[(2 * NPOS) * 32 + lane]);
                        s.x += e.x; s.y += e.y; s.z += e.z; s.w += e.w;
                    }
                }
                ((float4*)buf)[col * 32 + lane] = s;        // STS.128, conflict-free
            }
            __syncthreads();   // tile complete

            if (tid == 0) {
                asm volatile("fence.proxy.async.shared::cta;" ::: "memory");
                #pragma unroll 1
                for (int q = 0; q < r; ++q) {
                    const float* dst = out + unit_base + (size_t)(t + q) * TCOLS * CZ;
                    uint64_t gdst;
                    asm("cvta.to.global.u64 %0, %1;" : "=l"(gdst) : "l"(dst));
                    asm volatile(
                        "cp.async.bulk.global.shared::cta.bulk_group [%0], [%1], %2;"
                        :: "l"(gdst), "r"(bufaddr), "r"((uint32_t)TILE_BYTES)
                        : "memory");
                }
                // ONE group per buffer use -> ring accounting unchanged.
                asm volatile("cp.async.bulk.commit_group;" ::: "memory");
            }
            if (++b == NBUF) b = 0;
            t += r;
        }
    }
    // Outstanding bulk stores complete before kernel completion is visible.
}

// Generic fallback (any N): one thread per output float4, direct gathers.
__global__ void relpos_simple(const int* __restrict__ asym,
                              const int* __restrict__ resi,
                              const int* __restrict__ ent,
                              const int* __restrict__ sym,
                              const int* __restrict__ tok,
                              const float* __restrict__ W,
                              float* __restrict__ out,
                              int N)
{
    long long idx = (long long)blockIdx.x * blockDim.x + threadIdx.x;
    long long tot = (long long)N * N * (CZ / 4);
    if (idx >= tot) return;
    int f4 = (int)(idx & (CZ / 4 - 1));
    long long ij = idx >> 5;
    int j = (int)(ij % N);
    int i = (int)(ij / N);

    int p = pack_idx(asym[i], resi[i], ent[i], sym[i], tok[i],
                     asym[j], resi[j], ent[j], sym[j], tok[j]);
    int rU   = p & 0xFF;
    int cRel = p >> 8;
    const float4* W4 = (const float4*)W;
    float4 a  = W4[rU * 32 + f4];
    float4 x1 = (rU < NPOS) ? W4[(NPOS + 65) * 32 + f4] : W4[32 * 32 + f4];
    float4 ch = W4[(2 * NPOS + 1 + cRel) * 32 + f4];
    float4 s;
    s.x = a.x + x1.x + ch.x;
    s.y = a.y + x1.y + ch.y;
    s.z = a.z + x1.z + ch.z;
    s.w = a.w + x1.w + ch.w;
    if (cRel < 5) {
        float4 e = W4[(2 * NPOS) * 32 + f4];
        s.x += e.x; s.y += e.y; s.z += e.z; s.w += e.w;
    }
    ((float4*)out)[idx] = s;
}

extern "C" void kernel_launch(void* const* d_in, const int* in_sizes, int n_in,
                              void* d_out, int out_size)
{
    const int*   asym = (const int*)d_in[0];
    const int*   resi = (const int*)d_in[1];
    const int*   ent  = (const int*)d_in[2];
    const int*   sym  = (const int*)d_in[3];
    const int*   tok  = (const int*)d_in[4];
    const float* W    = (const float*)d_in[5];
    float*       out  = (float*)d_out;

    const int N = in_sizes[0];                  // B*N with B==1 -> 1024

    if (N == NN) {
        int nsm = 148;
        cudaDeviceGetAttribute(&nsm, cudaDevAttrMultiProcessorCount, 0);
        const int nUnits = (NN / HALF) * NN;
        int grid = 2 * nsm;
        if (grid > nUnits) grid = nUnits;

        const int smem_bytes = NBUF * TILE_BYTES + HALF * (int)sizeof(int)
                             + NTILE * (int)sizeof(int);
        cudaFuncSetAttribute(relpos_tma,
                             cudaFuncAttributeMaxDynamicSharedMemorySize, smem_bytes);
        relpos_tma<<<grid, 1024, smem_bytes>>>(asym, resi, ent, sym, tok, W, out);
    } else {
        long long tot = (long long)N * N * (CZ / 4);
        int grid = (int)((tot + 255) / 256);
        relpos_simple<<<grid, 256>>>(asym, resi, ent, sym, tok, W, out, N);
    }
}